// round 13
// baseline (speedup 1.0000x reference)
#include <cuda_runtime.h>
#include <cstdint>

// Problem constants (B=2, S=256, H=1024, V=131072, C=512, TOP_K=2)
#define NT   512      // B*S tokens
#define HD   1024     // hidden
#define NC   512      // centroids
#define NV   131072   // vocab
#define VPC  256      // vocab per centroid = NV/NC
#define TOPK 2
#define SPLIT 8       // row-split of each cluster in k_gather (32 rows/block)

// ---- scratch (no allocations allowed) ----
__device__ float    g_lg[NT * NC];           // routing logits [t][c]
__device__ int      g_top2[NT * TOPK];       // top-2 cluster ids per token
__device__ int      g_count[NC];             // tokens routed to each cluster
__device__ int      g_list[NC * NT];         // packed (token<<1)|k per cluster
__device__ float    g_sel[NT * TOPK * VPC];  // selected logits [t][k][r]
__device__ unsigned g_minkey;                // order-preserving-encoded global min
__device__ int      g_ident;                 // token_ordering == arange?

// order-preserving float<->uint mapping (monotone for unsigned compare)
__device__ __forceinline__ unsigned enc_f(float f) {
    unsigned u = __float_as_uint(f);
    return (u & 0x80000000u) ? ~u : (u | 0x80000000u);
}
__device__ __forceinline__ float dec_f(unsigned u) {
    return __uint_as_float((u & 0x80000000u) ? (u ^ 0x80000000u) : ~u);
}

__device__ __forceinline__ void prefetch_l2(const void* p) {
    asm volatile("prefetch.global.L2 [%0];" :: "l"(p));
}

// ---------------------------------------------------------------------------
// K1a: routing logits GEMM  g_lg[t][c] = <hs[t], cw[c]>  (R5 proven form)
// Block (0,0) additionally: re-init counters/minkey and verify ordering
// is the identity permutation (hidden under the other 255 blocks' GEMM).
// ---------------------------------------------------------------------------
#define KC 64
__global__ void __launch_bounds__(256) k_logits(const float* __restrict__ hs,
                                                const float* __restrict__ cw,
                                                const int* __restrict__ ordering) {
    __shared__ float As[32][KC + 1];
    __shared__ float Bs[32][KC + 1];
    int bx = blockIdx.x;              // centroid tile
    int by = blockIdx.y;              // token tile
    int tid = threadIdx.x;
    int tx = tid & 15, ty = tid >> 4;

    if (bx == 0 && by == 0) {         // fused init + identity check
        g_count[tid] = 0;
        g_count[tid + 256] = 0;
        if (tid == 0) { g_minkey = 0xFFFFFFFFu; g_ident = 1; }
        __syncthreads();
        int ok = 1;
        const int4* o4 = reinterpret_cast<const int4*>(ordering);
        for (int i = tid; i < NV / 4; i += 256) {
            int4 v = o4[i];
            int b = i * 4;
            ok &= (v.x == b) & (v.y == b + 1) & (v.z == b + 2) & (v.w == b + 3);
        }
        if (!ok) atomicAnd(&g_ident, 0);
    }

    float acc00 = 0.f, acc01 = 0.f, acc10 = 0.f, acc11 = 0.f;

    for (int kc = 0; kc < HD; kc += KC) {
        __syncthreads();
        #pragma unroll
        for (int l = tid; l < 512; l += 256) {
            int row = l >> 4, kq = (l & 15) << 2;
            float4 a = *reinterpret_cast<const float4*>(
                &hs[(size_t)(by * 32 + row) * HD + kc + kq]);
            As[row][kq] = a.x; As[row][kq + 1] = a.y;
            As[row][kq + 2] = a.z; As[row][kq + 3] = a.w;
            float4 b = *reinterpret_cast<const float4*>(
                &cw[(size_t)(bx * 32 + row) * HD + kc + kq]);
            Bs[row][kq] = b.x; Bs[row][kq + 1] = b.y;
            Bs[row][kq + 2] = b.z; Bs[row][kq + 3] = b.w;
        }
        __syncthreads();
        #pragma unroll
        for (int kk = 0; kk < KC; kk++) {
            float a0 = As[ty * 2][kk],     a1 = As[ty * 2 + 1][kk];
            float b0 = Bs[tx * 2][kk],     b1 = Bs[tx * 2 + 1][kk];
            acc00 += b0 * a0; acc01 += b0 * a1;
            acc10 += b1 * a0; acc11 += b1 * a1;
        }
    }
    int t = by * 32 + ty * 2, c = bx * 32 + tx * 2;
    g_lg[(size_t)t * NC + c]            = acc00;
    g_lg[(size_t)t * NC + c + 1]        = acc10;
    g_lg[(size_t)(t + 1) * NC + c]      = acc01;
    g_lg[(size_t)(t + 1) * NC + c + 1]  = acc11;
}

// ---------------------------------------------------------------------------
// K1b: top-2 per token + build per-cluster token lists. warp per token.
// ---------------------------------------------------------------------------
__global__ void __launch_bounds__(256) k_top2() {
    int warp = threadIdx.x >> 5, lane = threadIdx.x & 31;
    int t = blockIdx.x * 8 + warp;
    const float* row = g_lg + (size_t)t * NC;

    float bv = -__int_as_float(0x7f800000);
    int   bi = 0x7FFFFFFF;
    for (int c = lane; c < NC; c += 32) {
        float v = row[c];
        if (v > bv || (v == bv && c < bi)) { bv = v; bi = c; }
    }
    #pragma unroll
    for (int o = 16; o; o >>= 1) {
        float ov = __shfl_xor_sync(0xFFFFFFFFu, bv, o);
        int   oi = __shfl_xor_sync(0xFFFFFFFFu, bi, o);
        if (ov > bv || (ov == bv && oi < bi)) { bv = ov; bi = oi; }
    }
    int i0 = bi;
    bv = -__int_as_float(0x7f800000);
    bi = 0x7FFFFFFF;
    for (int c = lane; c < NC; c += 32) {
        if (c == i0) continue;
        float v = row[c];
        if (v > bv || (v == bv && c < bi)) { bv = v; bi = c; }
    }
    #pragma unroll
    for (int o = 16; o; o >>= 1) {
        float ov = __shfl_xor_sync(0xFFFFFFFFu, bv, o);
        int   oi = __shfl_xor_sync(0xFFFFFFFFu, bi, o);
        if (ov > bv || (ov == bv && oi < bi)) { bv = ov; bi = oi; }
    }
    int i1 = bi;

    if (lane == 0) {
        g_top2[t * 2 + 0] = i0;
        g_top2[t * 2 + 1] = i1;
        int p0 = atomicAdd(&g_count[i0], 1);
        g_list[i0 * NT + p0] = (t << 1);
        int p1 = atomicAdd(&g_count[i1], 1);
        g_list[i1 * NT + p1] = (t << 1) | 1;
    }
}

// ---------------------------------------------------------------------------
// K2: cluster-major candidate logits — exact R7 operating point (82.5us best).
// Two cached rows/warp, 16-line L2 prefetch of next rows, no occupancy cap.
// ---------------------------------------------------------------------------
#define TCH 8
__global__ void __launch_bounds__(128) k_gather(const float* __restrict__ hs,
                                                const float* __restrict__ W,
                                                const int* __restrict__ ordering) {
    int c = blockIdx.x;
    int n = g_count[c];
    if (n == 0) return;
    int r0 = blockIdx.y * (VPC / SPLIT);   // 32-row slice

    __shared__ float4 hsm[TCH][HD / 4];    // 32 KB
    __shared__ int    meta[TCH];
    __shared__ unsigned s_min[4];

    int tid = threadIdx.x, warp = tid >> 5, lane = tid & 31;
    unsigned lmin = 0xFFFFFFFFu;

    for (int t0 = 0; t0 < n; t0 += TCH) {
        int ncur = min(TCH, n - t0);
        __syncthreads();
        for (int e = tid; e < ncur * (HD / 4); e += 128) {
            int tt = e >> 8, j = e & 255;
            int pk = g_list[c * NT + t0 + tt];
            hsm[tt][j] = reinterpret_cast<const float4*>(hs)[(size_t)(pk >> 1) * (HD / 4) + j];
        }
        if (tid < ncur) meta[tid] = g_list[c * NT + t0 + tid];
        __syncthreads();

        #pragma unroll 1
        for (int it = 0; it < (VPC / SPLIT) / 8; it++) {
            int r = r0 + warp * 2 + it * 8;
            int vocab0 = __ldg(&ordering[c * VPC + r]);
            int vocab1 = __ldg(&ordering[c * VPC + r + 1]);
            const float4* wr0 = reinterpret_cast<const float4*>(W + (size_t)vocab0 * HD);
            const float4* wr1 = reinterpret_cast<const float4*>(W + (size_t)vocab1 * HD);
            float4 rv0[8], rv1[8];
            #pragma unroll
            for (int q = 0; q < 8; q++) rv0[q] = __ldcs(&wr0[lane + 32 * q]);
            #pragma unroll
            for (int q = 0; q < 8; q++) rv1[q] = __ldcs(&wr1[lane + 32 * q]);

            // prefetch next iteration's two rows to L2 (lanes 0-15, 1 line each)
            if (it + 1 < (VPC / SPLIT) / 8) {
                int rn = r + 8;
                int nv0 = __ldg(&ordering[c * VPC + rn]);
                int nv1 = __ldg(&ordering[c * VPC + rn + 1]);
                if (lane < 16) {
                    const char* base = reinterpret_cast<const char*>(
                        W + (size_t)(lane < 8 ? nv0 : nv1) * HD);
                    prefetch_l2(base + (size_t)(lane & 7) * 512);
                }
            }

            for (int e = 0; e < ncur; e++) {
                float p0 = 0.f, p1 = 0.f;
                #pragma unroll
                for (int q = 0; q < 8; q++) {
                    float4 hv = hsm[e][lane + 32 * q];
                    p0 += rv0[q].x * hv.x + rv0[q].y * hv.y + rv0[q].z * hv.z + rv0[q].w * hv.w;
                    p1 += rv1[q].x * hv.x + rv1[q].y * hv.y + rv1[q].z * hv.z + rv1[q].w * hv.w;
                }
                #pragma unroll
                for (int o = 16; o; o >>= 1) {
                    p0 += __shfl_xor_sync(0xFFFFFFFFu, p0, o);
                    p1 += __shfl_xor_sync(0xFFFFFFFFu, p1, o);
                }
                if (lane == 0) {
                    int pk = meta[e];
                    int t = pk >> 1, k = pk & 1;
                    *reinterpret_cast<float2*>(
                        &g_sel[(size_t)t * (TOPK * VPC) + k * VPC + r]) = make_float2(p0, p1);
                    unsigned k0 = enc_f(p0), k1 = enc_f(p1);
                    unsigned kk = min(k0, k1);
                    if (kk < lmin) lmin = kk;
                }
            }
        }
    }

    #pragma unroll
    for (int o = 16; o; o >>= 1) {
        unsigned ov = __shfl_xor_sync(0xFFFFFFFFu, lmin, o);
        if (ov < lmin) lmin = ov;
    }
    if (lane == 0) s_min[warp] = lmin;
    __syncthreads();
    if (tid == 0) {
        unsigned m = min(min(s_min[0], s_min[1]), min(s_min[2], s_min[3]));
        atomicMin(&g_minkey, m);
    }
}

// ---------------------------------------------------------------------------
// K3a: streaming mask fill + (identity path) in-block candidate overlay.
// Block = (token t, segment s): 8192 floats = 32 clusters' worth of vocab.
// If ordering is identity, the candidate ranges of t that fall in [s*8192,
// (s+1)*8192) are 256-float contiguous runs -> written here; scatter skips.
// ---------------------------------------------------------------------------
__global__ void __launch_bounds__(256) k_fillmask(float4* __restrict__ out) {
    __shared__ float s_mask;
    __shared__ int s_c0, s_c1, s_ident;
    int bid = blockIdx.x;
    int t = bid >> 4;         // 16 blocks per token (131072 floats / 8192)
    int s = bid & 15;
    if (threadIdx.x == 0) {
        s_mask = dec_f(g_minkey) - 1.0f;
        s_c0 = g_top2[t * 2 + 0];
        s_c1 = g_top2[t * 2 + 1];
        s_ident = g_ident;
    }
    __syncthreads();
    float m = s_mask;
    float4 mv = make_float4(m, m, m, m);
    size_t base = (size_t)bid * 2048 + threadIdx.x;
    #pragma unroll
    for (int j = 0; j < 8; j++) __stwt(&out[base + j * 256], mv);

    if (s_ident) {
        __syncthreads();      // mask stores of this block done
        int tid = threadIdx.x;
        if (tid < 128) {
            int k = tid >> 6;              // 0 -> c0, 1 -> c1
            int lane = tid & 63;
            int c = k ? s_c1 : s_c0;
            if ((c >> 5) == s) {           // cluster's 256-run is in this segment
                const float4* sel4 = reinterpret_cast<const float4*>(g_sel);
                float4 v = sel4[(size_t)t * 128 + k * 64 + lane];
                out[(size_t)t * 32768 + s * 2048 + (c & 31) * 64 + lane] = v;
            }
        }
    }
}

// ---------------------------------------------------------------------------
// K3b: scatter fallback for non-identity orderings (early-exit when identity).
// ---------------------------------------------------------------------------
__global__ void __launch_bounds__(512) k_scatter(float* __restrict__ out,
                                                 const int* __restrict__ ordering) {
    if (g_ident) return;
    int t = blockIdx.x;
    int tid = threadIdx.x;          // = k*256 + r
    int k = tid >> 8, r = tid & 255;
    int c = g_top2[t * 2 + k];
    int v = __ldg(&ordering[c * VPC + r]);
    out[(size_t)t * NV + v] = g_sel[(size_t)t * (TOPK * VPC) + tid];
}

// ---------------------------------------------------------------------------
extern "C" void kernel_launch(void* const* d_in, const int* in_sizes, int n_in,
                              void* d_out, int out_size) {
    const float* hs = (const float*)d_in[0];  // [2,256,1024]
    const float* W  = (const float*)d_in[1];  // [131072,1024]
    const float* cw = (const float*)d_in[2];  // [512,1024]
    const int*   to = (const int*)d_in[3];    // [131072]
    float* out = (float*)d_out;               // [2,256,131072]

    k_logits<<<dim3(NC / 32, NT / 32), 256>>>(hs, cw, to);
    k_top2<<<NT / 8, 256>>>();
    k_gather<<<dim3(NC, SPLIT), 128>>>(hs, W, to);
    k_fillmask<<<(unsigned)((size_t)NT * NV / 4 / 2048), 256>>>((float4*)out);
    k_scatter<<<NT, 512>>>(out, to);
}

// round 14
// speedup vs baseline: 1.0367x; 1.0367x over previous
#include <cuda_runtime.h>
#include <cstdint>

// Problem constants (B=2, S=256, H=1024, V=131072, C=512, TOP_K=2)
#define NT   512      // B*S tokens
#define HD   1024     // hidden
#define NC   512      // centroids
#define NV   131072   // vocab
#define VPC  256      // vocab per centroid = NV/NC
#define TOPK 2
#define SPLIT 8       // row-split of each cluster in k_gather (32 rows/block)

// ---- scratch (no allocations allowed) ----
__device__ float    g_lg[NT * NC];           // routing logits [t][c]
__device__ int      g_top2[NT * TOPK];       // top-2 cluster ids per token
__device__ int      g_count[NC];             // tokens routed to each cluster
__device__ int      g_list[NC * NT];         // packed (token<<1)|k per cluster
__device__ float    g_sel[NT * TOPK * VPC];  // selected logits [t][k][r]
__device__ unsigned g_minkey;                // order-preserving-encoded global min

// order-preserving float<->uint mapping (monotone for unsigned compare)
__device__ __forceinline__ unsigned enc_f(float f) {
    unsigned u = __float_as_uint(f);
    return (u & 0x80000000u) ? ~u : (u | 0x80000000u);
}
__device__ __forceinline__ float dec_f(unsigned u) {
    return __uint_as_float((u & 0x80000000u) ? (u ^ 0x80000000u) : ~u);
}

__device__ __forceinline__ void prefetch_l2(const void* p) {
    asm volatile("prefetch.global.L2 [%0];" :: "l"(p));
}

// ---------------------------------------------------------------------------
// K1a: routing logits GEMM  g_lg[t][c] = <hs[t], cw[c]>  (R5 proven form)
// Block (0,0) also re-inits counters/minkey (2KB of stores — negligible).
// ---------------------------------------------------------------------------
#define KC 64
__global__ void __launch_bounds__(256) k_logits(const float* __restrict__ hs,
                                                const float* __restrict__ cw) {
    __shared__ float As[32][KC + 1];
    __shared__ float Bs[32][KC + 1];
    int bx = blockIdx.x;              // centroid tile
    int by = blockIdx.y;              // token tile
    int tid = threadIdx.x;
    int tx = tid & 15, ty = tid >> 4;

    if (bx == 0 && by == 0) {         // fused init (cheap: 513 words)
        g_count[tid] = 0;
        g_count[tid + 256] = 0;
        if (tid == 0) g_minkey = 0xFFFFFFFFu;
    }

    float acc00 = 0.f, acc01 = 0.f, acc10 = 0.f, acc11 = 0.f;

    for (int kc = 0; kc < HD; kc += KC) {
        __syncthreads();
        #pragma unroll
        for (int l = tid; l < 512; l += 256) {
            int row = l >> 4, kq = (l & 15) << 2;
            float4 a = *reinterpret_cast<const float4*>(
                &hs[(size_t)(by * 32 + row) * HD + kc + kq]);
            As[row][kq] = a.x; As[row][kq + 1] = a.y;
            As[row][kq + 2] = a.z; As[row][kq + 3] = a.w;
            float4 b = *reinterpret_cast<const float4*>(
                &cw[(size_t)(bx * 32 + row) * HD + kc + kq]);
            Bs[row][kq] = b.x; Bs[row][kq + 1] = b.y;
            Bs[row][kq + 2] = b.z; Bs[row][kq + 3] = b.w;
        }
        __syncthreads();
        #pragma unroll
        for (int kk = 0; kk < KC; kk++) {
            float a0 = As[ty * 2][kk],     a1 = As[ty * 2 + 1][kk];
            float b0 = Bs[tx * 2][kk],     b1 = Bs[tx * 2 + 1][kk];
            acc00 += b0 * a0; acc01 += b0 * a1;
            acc10 += b1 * a0; acc11 += b1 * a1;
        }
    }
    int t = by * 32 + ty * 2, c = bx * 32 + tx * 2;
    g_lg[(size_t)t * NC + c]            = acc00;
    g_lg[(size_t)t * NC + c + 1]        = acc10;
    g_lg[(size_t)(t + 1) * NC + c]      = acc01;
    g_lg[(size_t)(t + 1) * NC + c + 1]  = acc11;
}

// ---------------------------------------------------------------------------
// K1b: top-2 per token + build per-cluster token lists. warp per token.
// ---------------------------------------------------------------------------
__global__ void __launch_bounds__(256) k_top2() {
    int warp = threadIdx.x >> 5, lane = threadIdx.x & 31;
    int t = blockIdx.x * 8 + warp;
    const float* row = g_lg + (size_t)t * NC;

    float bv = -__int_as_float(0x7f800000);
    int   bi = 0x7FFFFFFF;
    for (int c = lane; c < NC; c += 32) {
        float v = row[c];
        if (v > bv || (v == bv && c < bi)) { bv = v; bi = c; }
    }
    #pragma unroll
    for (int o = 16; o; o >>= 1) {
        float ov = __shfl_xor_sync(0xFFFFFFFFu, bv, o);
        int   oi = __shfl_xor_sync(0xFFFFFFFFu, bi, o);
        if (ov > bv || (ov == bv && oi < bi)) { bv = ov; bi = oi; }
    }
    int i0 = bi;
    bv = -__int_as_float(0x7f800000);
    bi = 0x7FFFFFFF;
    for (int c = lane; c < NC; c += 32) {
        if (c == i0) continue;
        float v = row[c];
        if (v > bv || (v == bv && c < bi)) { bv = v; bi = c; }
    }
    #pragma unroll
    for (int o = 16; o; o >>= 1) {
        float ov = __shfl_xor_sync(0xFFFFFFFFu, bv, o);
        int   oi = __shfl_xor_sync(0xFFFFFFFFu, bi, o);
        if (ov > bv || (ov == bv && oi < bi)) { bv = ov; bi = oi; }
    }
    int i1 = bi;

    if (lane == 0) {
        g_top2[t * 2 + 0] = i0;
        g_top2[t * 2 + 1] = i1;
        int p0 = atomicAdd(&g_count[i0], 1);
        g_list[i0 * NT + p0] = (t << 1);
        int p1 = atomicAdd(&g_count[i1], 1);
        g_list[i1 * NT + p1] = (t << 1) | 1;
    }
}

// ---------------------------------------------------------------------------
// K2: cluster-major candidate logits — exact R7 operating point (82.5us best).
// Two cached rows/warp, 16-line L2 prefetch of next rows, no occupancy cap.
// ---------------------------------------------------------------------------
#define TCH 8
__global__ void __launch_bounds__(128) k_gather(const float* __restrict__ hs,
                                                const float* __restrict__ W,
                                                const int* __restrict__ ordering) {
    int c = blockIdx.x;
    int n = g_count[c];
    if (n == 0) return;
    int r0 = blockIdx.y * (VPC / SPLIT);   // 32-row slice

    __shared__ float4 hsm[TCH][HD / 4];    // 32 KB
    __shared__ int    meta[TCH];
    __shared__ unsigned s_min[4];

    int tid = threadIdx.x, warp = tid >> 5, lane = tid & 31;
    unsigned lmin = 0xFFFFFFFFu;

    for (int t0 = 0; t0 < n; t0 += TCH) {
        int ncur = min(TCH, n - t0);
        __syncthreads();
        for (int e = tid; e < ncur * (HD / 4); e += 128) {
            int tt = e >> 8, j = e & 255;
            int pk = g_list[c * NT + t0 + tt];
            hsm[tt][j] = reinterpret_cast<const float4*>(hs)[(size_t)(pk >> 1) * (HD / 4) + j];
        }
        if (tid < ncur) meta[tid] = g_list[c * NT + t0 + tid];
        __syncthreads();

        #pragma unroll 1
        for (int it = 0; it < (VPC / SPLIT) / 8; it++) {
            int r = r0 + warp * 2 + it * 8;
            int vocab0 = __ldg(&ordering[c * VPC + r]);
            int vocab1 = __ldg(&ordering[c * VPC + r + 1]);
            const float4* wr0 = reinterpret_cast<const float4*>(W + (size_t)vocab0 * HD);
            const float4* wr1 = reinterpret_cast<const float4*>(W + (size_t)vocab1 * HD);
            float4 rv0[8], rv1[8];
            #pragma unroll
            for (int q = 0; q < 8; q++) rv0[q] = __ldcs(&wr0[lane + 32 * q]);
            #pragma unroll
            for (int q = 0; q < 8; q++) rv1[q] = __ldcs(&wr1[lane + 32 * q]);

            // prefetch next iteration's two rows to L2 (lanes 0-15, 1 line each)
            if (it + 1 < (VPC / SPLIT) / 8) {
                int rn = r + 8;
                int nv0 = __ldg(&ordering[c * VPC + rn]);
                int nv1 = __ldg(&ordering[c * VPC + rn + 1]);
                if (lane < 16) {
                    const char* base = reinterpret_cast<const char*>(
                        W + (size_t)(lane < 8 ? nv0 : nv1) * HD);
                    prefetch_l2(base + (size_t)(lane & 7) * 512);
                }
            }

            for (int e = 0; e < ncur; e++) {
                float p0 = 0.f, p1 = 0.f;
                #pragma unroll
                for (int q = 0; q < 8; q++) {
                    float4 hv = hsm[e][lane + 32 * q];
                    p0 += rv0[q].x * hv.x + rv0[q].y * hv.y + rv0[q].z * hv.z + rv0[q].w * hv.w;
                    p1 += rv1[q].x * hv.x + rv1[q].y * hv.y + rv1[q].z * hv.z + rv1[q].w * hv.w;
                }
                #pragma unroll
                for (int o = 16; o; o >>= 1) {
                    p0 += __shfl_xor_sync(0xFFFFFFFFu, p0, o);
                    p1 += __shfl_xor_sync(0xFFFFFFFFu, p1, o);
                }
                if (lane == 0) {
                    int pk = meta[e];
                    int t = pk >> 1, k = pk & 1;
                    *reinterpret_cast<float2*>(
                        &g_sel[(size_t)t * (TOPK * VPC) + k * VPC + r]) = make_float2(p0, p1);
                    unsigned k0 = enc_f(p0), k1 = enc_f(p1);
                    unsigned kk = min(k0, k1);
                    if (kk < lmin) lmin = kk;
                }
            }
        }
    }

    #pragma unroll
    for (int o = 16; o; o >>= 1) {
        unsigned ov = __shfl_xor_sync(0xFFFFFFFFu, lmin, o);
        if (ov < lmin) lmin = ov;
    }
    if (lane == 0) s_min[warp] = lmin;
    __syncthreads();
    if (tid == 0) {
        unsigned m = min(min(s_min[0], s_min[1]), min(s_min[2], s_min[3]));
        atomicMin(&g_minkey, m);
    }
}

// ---------------------------------------------------------------------------
// K3a: pure streaming mask fill, 8 float4 (128B) per thread, __stwt.
// (R10 exact: 39.2us measured — at the write floor.)
// ---------------------------------------------------------------------------
__global__ void __launch_bounds__(256) k_fillmask(float4* __restrict__ out) {
    __shared__ float s_mask;
    if (threadIdx.x == 0) s_mask = dec_f(g_minkey) - 1.0f;
    __syncthreads();
    float m = s_mask;
    float4 mv = make_float4(m, m, m, m);
    size_t base = (size_t)blockIdx.x * 2048 + threadIdx.x;
    #pragma unroll
    for (int j = 0; j < 8; j++) __stwt(&out[base + j * 256], mv);
}

// ---------------------------------------------------------------------------
// K3b: scatter candidate logits over the mask. One block per token,
// 512 threads = (k,r).
// ---------------------------------------------------------------------------
__global__ void __launch_bounds__(512) k_scatter(float* __restrict__ out,
                                                 const int* __restrict__ ordering) {
    int t = blockIdx.x;
    int tid = threadIdx.x;          // = k*256 + r
    int k = tid >> 8, r = tid & 255;
    int c = g_top2[t * 2 + k];
    int v = __ldg(&ordering[c * VPC + r]);
    out[(size_t)t * NV + v] = g_sel[(size_t)t * (TOPK * VPC) + tid];
}

// ---------------------------------------------------------------------------
extern "C" void kernel_launch(void* const* d_in, const int* in_sizes, int n_in,
                              void* d_out, int out_size) {
    const float* hs = (const float*)d_in[0];  // [2,256,1024]
    const float* W  = (const float*)d_in[1];  // [131072,1024]
    const float* cw = (const float*)d_in[2];  // [512,1024]
    const int*   to = (const int*)d_in[3];    // [131072]
    float* out = (float*)d_out;               // [2,256,131072]

    k_logits<<<dim3(NC / 32, NT / 32), 256>>>(hs, cw);
    k_top2<<<NT / 8, 256>>>();
    k_gather<<<dim3(NC, SPLIT), 128>>>(hs, W, to);
    k_fillmask<<<(unsigned)((size_t)NT * NV / 4 / 2048), 256>>>((float4*)out);
    k_scatter<<<NT, 512>>>(out, to);
}

// round 15
// speedup vs baseline: 1.0391x; 1.0024x over previous
#include <cuda_runtime.h>
#include <cstdint>

// Problem constants (B=2, S=256, H=1024, V=131072, C=512, TOP_K=2)
#define NT   512      // B*S tokens
#define HD   1024     // hidden
#define NC   512      // centroids
#define NV   131072   // vocab
#define VPC  256      // vocab per centroid = NV/NC
#define TOPK 2
#define SPLIT 8       // row-split of each cluster in k_gather (32 rows/block)

// ---- scratch (no allocations allowed) ----
__device__ float    g_lg[NT * NC];           // routing logits [t][c]
__device__ int      g_top2[NT * TOPK];       // top-2 cluster ids per token
__device__ int      g_count[NC];             // tokens routed to each cluster
__device__ int      g_list[NC * NT];         // packed (token<<1)|k per cluster
__device__ float    g_sel[NT * TOPK * VPC];  // selected logits [t][k][r]
__device__ unsigned g_minkey;                // order-preserving-encoded global min

// order-preserving float<->uint mapping (monotone for unsigned compare)
__device__ __forceinline__ unsigned enc_f(float f) {
    unsigned u = __float_as_uint(f);
    return (u & 0x80000000u) ? ~u : (u | 0x80000000u);
}
__device__ __forceinline__ float dec_f(unsigned u) {
    return __uint_as_float((u & 0x80000000u) ? (u ^ 0x80000000u) : ~u);
}

__device__ __forceinline__ void prefetch_l2(const void* p) {
    asm volatile("prefetch.global.L2 [%0];" :: "l"(p));
}

// ---------------------------------------------------------------------------
// K1a: routing logits GEMM  g_lg[t][c] = <hs[t], cw[c]>  (R5 proven form)
// Block (0,0) also re-inits counters/minkey (2KB of stores — negligible).
// ---------------------------------------------------------------------------
#define KC 64
__global__ void __launch_bounds__(256) k_logits(const float* __restrict__ hs,
                                                const float* __restrict__ cw) {
    __shared__ float As[32][KC + 1];
    __shared__ float Bs[32][KC + 1];
    int bx = blockIdx.x;              // centroid tile
    int by = blockIdx.y;              // token tile
    int tid = threadIdx.x;
    int tx = tid & 15, ty = tid >> 4;

    if (bx == 0 && by == 0) {         // fused init (cheap: 513 words)
        g_count[tid] = 0;
        g_count[tid + 256] = 0;
        if (tid == 0) g_minkey = 0xFFFFFFFFu;
    }

    float acc00 = 0.f, acc01 = 0.f, acc10 = 0.f, acc11 = 0.f;

    for (int kc = 0; kc < HD; kc += KC) {
        __syncthreads();
        #pragma unroll
        for (int l = tid; l < 512; l += 256) {
            int row = l >> 4, kq = (l & 15) << 2;
            float4 a = *reinterpret_cast<const float4*>(
                &hs[(size_t)(by * 32 + row) * HD + kc + kq]);
            As[row][kq] = a.x; As[row][kq + 1] = a.y;
            As[row][kq + 2] = a.z; As[row][kq + 3] = a.w;
            float4 b = *reinterpret_cast<const float4*>(
                &cw[(size_t)(bx * 32 + row) * HD + kc + kq]);
            Bs[row][kq] = b.x; Bs[row][kq + 1] = b.y;
            Bs[row][kq + 2] = b.z; Bs[row][kq + 3] = b.w;
        }
        __syncthreads();
        #pragma unroll
        for (int kk = 0; kk < KC; kk++) {
            float a0 = As[ty * 2][kk],     a1 = As[ty * 2 + 1][kk];
            float b0 = Bs[tx * 2][kk],     b1 = Bs[tx * 2 + 1][kk];
            acc00 += b0 * a0; acc01 += b0 * a1;
            acc10 += b1 * a0; acc11 += b1 * a1;
        }
    }
    int t = by * 32 + ty * 2, c = bx * 32 + tx * 2;
    g_lg[(size_t)t * NC + c]            = acc00;
    g_lg[(size_t)t * NC + c + 1]        = acc10;
    g_lg[(size_t)(t + 1) * NC + c]      = acc01;
    g_lg[(size_t)(t + 1) * NC + c + 1]  = acc11;
}

// ---------------------------------------------------------------------------
// K1b: top-2 per token + build per-cluster token lists. warp per token.
// ---------------------------------------------------------------------------
__global__ void __launch_bounds__(256) k_top2() {
    int warp = threadIdx.x >> 5, lane = threadIdx.x & 31;
    int t = blockIdx.x * 8 + warp;
    const float* row = g_lg + (size_t)t * NC;

    float bv = -__int_as_float(0x7f800000);
    int   bi = 0x7FFFFFFF;
    for (int c = lane; c < NC; c += 32) {
        float v = row[c];
        if (v > bv || (v == bv && c < bi)) { bv = v; bi = c; }
    }
    #pragma unroll
    for (int o = 16; o; o >>= 1) {
        float ov = __shfl_xor_sync(0xFFFFFFFFu, bv, o);
        int   oi = __shfl_xor_sync(0xFFFFFFFFu, bi, o);
        if (ov > bv || (ov == bv && oi < bi)) { bv = ov; bi = oi; }
    }
    int i0 = bi;
    bv = -__int_as_float(0x7f800000);
    bi = 0x7FFFFFFF;
    for (int c = lane; c < NC; c += 32) {
        if (c == i0) continue;
        float v = row[c];
        if (v > bv || (v == bv && c < bi)) { bv = v; bi = c; }
    }
    #pragma unroll
    for (int o = 16; o; o >>= 1) {
        float ov = __shfl_xor_sync(0xFFFFFFFFu, bv, o);
        int   oi = __shfl_xor_sync(0xFFFFFFFFu, bi, o);
        if (ov > bv || (ov == bv && oi < bi)) { bv = ov; bi = oi; }
    }
    int i1 = bi;

    if (lane == 0) {
        g_top2[t * 2 + 0] = i0;
        g_top2[t * 2 + 1] = i1;
        int p0 = atomicAdd(&g_count[i0], 1);
        g_list[i0 * NT + p0] = (t << 1);
        int p1 = atomicAdd(&g_count[i1], 1);
        g_list[i1 * NT + p1] = (t << 1) | 1;
    }
}

// ---------------------------------------------------------------------------
// K2: cluster-major candidate logits — exact R7 operating point (82.5us best).
// Two cached rows/warp, 16-line L2 prefetch of next rows, no occupancy cap.
// ---------------------------------------------------------------------------
#define TCH 8
__global__ void __launch_bounds__(128) k_gather(const float* __restrict__ hs,
                                                const float* __restrict__ W,
                                                const int* __restrict__ ordering) {
    int c = blockIdx.x;
    int n = g_count[c];
    if (n == 0) return;
    int r0 = blockIdx.y * (VPC / SPLIT);   // 32-row slice

    __shared__ float4 hsm[TCH][HD / 4];    // 32 KB
    __shared__ int    meta[TCH];
    __shared__ unsigned s_min[4];

    int tid = threadIdx.x, warp = tid >> 5, lane = tid & 31;
    unsigned lmin = 0xFFFFFFFFu;

    for (int t0 = 0; t0 < n; t0 += TCH) {
        int ncur = min(TCH, n - t0);
        __syncthreads();
        for (int e = tid; e < ncur * (HD / 4); e += 128) {
            int tt = e >> 8, j = e & 255;
            int pk = g_list[c * NT + t0 + tt];
            hsm[tt][j] = reinterpret_cast<const float4*>(hs)[(size_t)(pk >> 1) * (HD / 4) + j];
        }
        if (tid < ncur) meta[tid] = g_list[c * NT + t0 + tid];
        __syncthreads();

        #pragma unroll 1
        for (int it = 0; it < (VPC / SPLIT) / 8; it++) {
            int r = r0 + warp * 2 + it * 8;
            int vocab0 = __ldg(&ordering[c * VPC + r]);
            int vocab1 = __ldg(&ordering[c * VPC + r + 1]);
            const float4* wr0 = reinterpret_cast<const float4*>(W + (size_t)vocab0 * HD);
            const float4* wr1 = reinterpret_cast<const float4*>(W + (size_t)vocab1 * HD);
            float4 rv0[8], rv1[8];
            #pragma unroll
            for (int q = 0; q < 8; q++) rv0[q] = __ldcs(&wr0[lane + 32 * q]);
            #pragma unroll
            for (int q = 0; q < 8; q++) rv1[q] = __ldcs(&wr1[lane + 32 * q]);

            // prefetch next iteration's two rows to L2 (lanes 0-15, 1 line each)
            if (it + 1 < (VPC / SPLIT) / 8) {
                int rn = r + 8;
                int nv0 = __ldg(&ordering[c * VPC + rn]);
                int nv1 = __ldg(&ordering[c * VPC + rn + 1]);
                if (lane < 16) {
                    const char* base = reinterpret_cast<const char*>(
                        W + (size_t)(lane < 8 ? nv0 : nv1) * HD);
                    prefetch_l2(base + (size_t)(lane & 7) * 512);
                }
            }

            for (int e = 0; e < ncur; e++) {
                float p0 = 0.f, p1 = 0.f;
                #pragma unroll
                for (int q = 0; q < 8; q++) {
                    float4 hv = hsm[e][lane + 32 * q];
                    p0 += rv0[q].x * hv.x + rv0[q].y * hv.y + rv0[q].z * hv.z + rv0[q].w * hv.w;
                    p1 += rv1[q].x * hv.x + rv1[q].y * hv.y + rv1[q].z * hv.z + rv1[q].w * hv.w;
                }
                #pragma unroll
                for (int o = 16; o; o >>= 1) {
                    p0 += __shfl_xor_sync(0xFFFFFFFFu, p0, o);
                    p1 += __shfl_xor_sync(0xFFFFFFFFu, p1, o);
                }
                if (lane == 0) {
                    int pk = meta[e];
                    int t = pk >> 1, k = pk & 1;
                    *reinterpret_cast<float2*>(
                        &g_sel[(size_t)t * (TOPK * VPC) + k * VPC + r]) = make_float2(p0, p1);
                    unsigned k0 = enc_f(p0), k1 = enc_f(p1);
                    unsigned kk = min(k0, k1);
                    if (kk < lmin) lmin = kk;
                }
            }
        }
    }

    #pragma unroll
    for (int o = 16; o; o >>= 1) {
        unsigned ov = __shfl_xor_sync(0xFFFFFFFFu, lmin, o);
        if (ov < lmin) lmin = ov;
    }
    if (lane == 0) s_min[warp] = lmin;
    __syncthreads();
    if (tid == 0) {
        unsigned m = min(min(s_min[0], s_min[1]), min(s_min[2], s_min[3]));
        atomicMin(&g_minkey, m);
    }
}

// ---------------------------------------------------------------------------
// K3a: pure streaming mask fill, 8 float4 (128B) per thread, __stwt.
// (R10 exact: 39.2us measured — at the write floor.)
// ---------------------------------------------------------------------------
__global__ void __launch_bounds__(256) k_fillmask(float4* __restrict__ out) {
    __shared__ float s_mask;
    if (threadIdx.x == 0) s_mask = dec_f(g_minkey) - 1.0f;
    __syncthreads();
    float m = s_mask;
    float4 mv = make_float4(m, m, m, m);
    size_t base = (size_t)blockIdx.x * 2048 + threadIdx.x;
    #pragma unroll
    for (int j = 0; j < 8; j++) __stwt(&out[base + j * 256], mv);
}

// ---------------------------------------------------------------------------
// K3b: scatter candidate logits over the mask. One block per token,
// 512 threads = (k,r).
// ---------------------------------------------------------------------------
__global__ void __launch_bounds__(512) k_scatter(float* __restrict__ out,
                                                 const int* __restrict__ ordering) {
    int t = blockIdx.x;
    int tid = threadIdx.x;          // = k*256 + r
    int k = tid >> 8, r = tid & 255;
    int c = g_top2[t * 2 + k];
    int v = __ldg(&ordering[c * VPC + r]);
    out[(size_t)t * NV + v] = g_sel[(size_t)t * (TOPK * VPC) + tid];
}

// ---------------------------------------------------------------------------
extern "C" void kernel_launch(void* const* d_in, const int* in_sizes, int n_in,
                              void* d_out, int out_size) {
    const float* hs = (const float*)d_in[0];  // [2,256,1024]
    const float* W  = (const float*)d_in[1];  // [131072,1024]
    const float* cw = (const float*)d_in[2];  // [512,1024]
    const int*   to = (const int*)d_in[3];    // [131072]
    float* out = (float*)d_out;               // [2,256,131072]

    k_logits<<<dim3(NC / 32, NT / 32), 256>>>(hs, cw);
    k_top2<<<NT / 8, 256>>>();
    k_gather<<<dim3(NC, SPLIT), 128>>>(hs, W, to);
    k_fillmask<<<(unsigned)((size_t)NT * NV / 4 / 2048), 256>>>((float4*)out);
    k_scatter<<<NT, 512>>>(out, to);
}